// round 1
// baseline (speedup 1.0000x reference)
#include <cuda_runtime.h>
#include <cuda_bf16.h>
#include <math.h>

// Problem constants
#define NB   16
#define NRW  300     // NR == NR_SO
#define CC   150
#define NREL 50
#define RR   3
#define RR2  9
#define NTRI 2700    // NRW * RR2
#define MAXR 100
#define KK   10

// Output float offsets inside d_out
#define O_PRO   0LL
#define O_BOX   2621440LL
#define O_CLS   2662400LL
#define O_REL   4198400LL
#define O_ROI   5509120LL
#define O_VIS   69734400LL

__device__ int g_ent[NB * KK];

__device__ __forceinline__ float sigmoidf_(float x) {
    return 1.0f / (1.0f + expf(-x));
}

// ---------------------------------------------------------------------------
// Selection kernel: one block per batch image.
// ---------------------------------------------------------------------------
__global__ void __launch_bounds__(512) select_kernel(
    const float* __restrict__ so_cls,     // (NB, 300, 300)
    const float* __restrict__ rel_logits, // (NB, 300, 50)
    const float* __restrict__ pb_so,      // (NB, 300, 8)
    const float* __restrict__ cls_logits, // (NB, 600, 150)
    const float* __restrict__ pred_bb,    // (NB, 600, 4)
    const unsigned char* __restrict__ vis,// (NB, 300) bool
    float* __restrict__ vis_out)          // (NB, 300) float region of d_out
{
    const int b   = blockIdx.x;
    const int tid = threadIdx.x;
    const int nthreads = blockDim.x;

    __shared__ float s_sc[NRW][RR];  __shared__ int s_cl[NRW][RR];
    __shared__ float o_sc[NRW][RR];  __shared__ int o_cl[NRW][RR];
    __shared__ float relmax[NRW];
    __shared__ float tri[NTRI];
    __shared__ unsigned char selflag[NTRI];
    __shared__ int   tri_idx_sh[MAXR];
    __shared__ int   selcls[2 * MAXR];
    __shared__ float selbox[2 * MAXR][4];
    __shared__ float entscore[NRW];
    __shared__ unsigned char entflag[NRW];
    __shared__ float red_v[16];
    __shared__ int   red_i[16];

    // ---- Phase 1: per-SO-row top-3 subject/object classes + rel_max ----
    for (int i = tid; i < NRW; i += nthreads) {
        const float* row = so_cls + ((long long)b * NRW + i) * (2 * CC);
        // subject = cols [0,150)
        {
            float v0 = -1e30f, v1 = -1e30f, v2 = -1e30f;
            int   i0 = 0, i1 = 0, i2 = 0;
            for (int c = 0; c < CC; c++) {
                float v = row[c];
                if (v > v0)      { v2 = v1; i2 = i1; v1 = v0; i1 = i0; v0 = v; i0 = c; }
                else if (v > v1) { v2 = v1; i2 = i1; v1 = v;  i1 = c; }
                else if (v > v2) { v2 = v;  i2 = c; }
            }
            s_sc[i][0] = sigmoidf_(v0); s_cl[i][0] = i0;
            s_sc[i][1] = sigmoidf_(v1); s_cl[i][1] = i1;
            s_sc[i][2] = sigmoidf_(v2); s_cl[i][2] = i2;
        }
        // object = cols [150,300)
        {
            float v0 = -1e30f, v1 = -1e30f, v2 = -1e30f;
            int   i0 = 0, i1 = 0, i2 = 0;
            for (int c = 0; c < CC; c++) {
                float v = row[CC + c];
                if (v > v0)      { v2 = v1; i2 = i1; v1 = v0; i1 = i0; v0 = v; i0 = c; }
                else if (v > v1) { v2 = v1; i2 = i1; v1 = v;  i1 = c; }
                else if (v > v2) { v2 = v;  i2 = c; }
            }
            o_sc[i][0] = sigmoidf_(v0); o_cl[i][0] = i0;
            o_sc[i][1] = sigmoidf_(v1); o_cl[i][1] = i1;
            o_sc[i][2] = sigmoidf_(v2); o_cl[i][2] = i2;
        }
        // rel_max = sigmoid(max logit)  (sigmoid is monotone)
        {
            const float* rl = rel_logits + ((long long)b * NRW + i) * NREL;
            float m = rl[0];
            for (int c = 1; c < NREL; c++) m = fmaxf(m, rl[c]);
            relmax[i] = sigmoidf_(m);
        }
    }
    __syncthreads();

    // ---- Phase 2: triple scores ----
    for (int t = tid; t < NTRI; t += nthreads) {
        int i = t / RR2, p = t % RR2;
        int X = p / RR,  Y = p % RR;
        tri[t] = (relmax[i] * s_sc[i][X]) * o_sc[i][Y];
        selflag[t] = 0;
    }
    __syncthreads();

    // ---- Phase 3: top-100 of 2700 (value desc, index asc on ties) ----
    for (int it = 0; it < MAXR; it++) {
        float bv = -1e30f; int bi = 0x7fffffff;
        for (int t = tid; t < NTRI; t += nthreads) {
            if (selflag[t]) continue;
            float v = tri[t];
            if (v > bv || (v == bv && t < bi)) { bv = v; bi = t; }
        }
        // warp reduce
        for (int o = 16; o > 0; o >>= 1) {
            float ov = __shfl_down_sync(0xffffffffu, bv, o);
            int   oi = __shfl_down_sync(0xffffffffu, bi, o);
            if (ov > bv || (ov == bv && oi < bi)) { bv = ov; bi = oi; }
        }
        if ((tid & 31) == 0) { red_v[tid >> 5] = bv; red_i[tid >> 5] = bi; }
        __syncthreads();
        if (tid == 0) {
            int nw = nthreads >> 5;
            float fv = red_v[0]; int fi = red_i[0];
            for (int w = 1; w < nw; w++)
                if (red_v[w] > fv || (red_v[w] == fv && red_i[w] < fi)) { fv = red_v[w]; fi = red_i[w]; }
            selflag[fi] = 1;
        }
        __syncthreads();
    }

    // ascending compaction == jnp.sort(tri_idx)
    if (tid == 0) {
        int m = 0;
        for (int t = 0; t < NTRI; t++) if (selflag[t]) tri_idx_sh[m++] = t;
    }
    __syncthreads();

    // ---- Phase 4: gather selected classes & boxes ----
    for (int m = tid; m < MAXR; m += nthreads) {
        int t = tri_idx_sh[m];
        int i = t / RR2, p = t % RR2;
        int X = p / RR,  Y = p % RR;
        selcls[2 * m]     = s_cl[i][X];
        selcls[2 * m + 1] = o_cl[i][Y];
        const float* bx = pb_so + ((long long)b * NRW + i) * 8;
        selbox[2 * m][0]     = bx[0]; selbox[2 * m][1]     = bx[1];
        selbox[2 * m][2]     = bx[2]; selbox[2 * m][3]     = bx[3];
        selbox[2 * m + 1][0] = bx[4]; selbox[2 * m + 1][1] = bx[5];
        selbox[2 * m + 1][2] = bx[6]; selbox[2 * m + 1][3] = bx[7];
    }
    __syncthreads();

    // ---- Phase 5: per-entity score ----
    for (int i = tid; i < NRW; i += nthreads) {
        const float* cr = cls_logits + ((long long)b * (2 * NRW) + 2 * i) * CC;
        float mx = cr[0]; int mi = 0;
        for (int c = 1; c < CC; c++) { float v = cr[c]; if (v > mx) { mx = v; mi = c; } }
        const float* bb = pred_bb + ((long long)b * (2 * NRW) + 2 * i) * 4;
        float x1 = bb[0], y1 = bb[1], x2 = bb[2], y2 = bb[3];
        float a1 = (y2 - y1 + 1.0f) * (x2 - x1 + 1.0f);
        bool isnew = true;
        for (int j = 0; j < 2 * MAXR; j++) {
            if (selcls[j] != mi) continue;
            float bx1 = selbox[j][0], by1 = selbox[j][1];
            float bx2 = selbox[j][2], by2 = selbox[j][3];
            float a2  = (by2 - by1 + 1.0f) * (bx2 - bx1 + 1.0f);
            float ltx = fmaxf(x1, bx1), lty = fmaxf(y1, by1);
            float rbx = fminf(x2, bx2), rby = fminf(y2, by2);
            float w = fmaxf(rbx - ltx, 0.0f), h = fmaxf(rby - lty, 0.0f);
            float inter = w * h;
            float iou = inter / (a1 + a2 - inter);
            if (iou >= 0.5f) { isnew = false; break; }
        }
        float sc = sigmoidf_(mx);
        if (!isnew) sc -= 2.0f;
        if (vis[b * NRW + i]) sc -= 2.0f;
        entscore[i] = sc;
        entflag[i]  = 0;
    }
    __syncthreads();

    // ---- Phase 6: top-10 entities ----
    for (int it = 0; it < KK; it++) {
        float bv = -1e30f; int bi = 0x7fffffff;
        for (int t = tid; t < NRW; t += nthreads) {
            if (entflag[t]) continue;
            float v = entscore[t];
            if (v > bv || (v == bv && t < bi)) { bv = v; bi = t; }
        }
        for (int o = 16; o > 0; o >>= 1) {
            float ov = __shfl_down_sync(0xffffffffu, bv, o);
            int   oi = __shfl_down_sync(0xffffffffu, bi, o);
            if (ov > bv || (ov == bv && oi < bi)) { bv = ov; bi = oi; }
        }
        if ((tid & 31) == 0) { red_v[tid >> 5] = bv; red_i[tid >> 5] = bi; }
        __syncthreads();
        if (tid == 0) {
            int nw = nthreads >> 5;
            float fv = red_v[0]; int fi = red_i[0];
            for (int w = 1; w < nw; w++)
                if (red_v[w] > fv || (red_v[w] == fv && red_i[w] < fi)) { fv = red_v[w]; fi = red_i[w]; }
            entflag[fi] = 1;
        }
        __syncthreads();
    }

    if (tid == 0) {
        int m = 0;
        for (int i = 0; i < NRW; i++) if (entflag[i]) g_ent[b * KK + m++] = i;
    }
    __syncthreads();

    // vis_out (float 0/1 in output buffer)
    for (int i = tid; i < NRW; i += nthreads)
        vis_out[b * NRW + i] = (vis[b * NRW + i] || entflag[i]) ? 1.0f : 0.0f;
}

// ---------------------------------------------------------------------------
// Fuse kernel: rows [0,300) copy from main src, rows [300,320) gather rows
// g_ent with a rotating column offset (handles half-swap AND the rel split).
// 2D grid: x covers columns (vector units), y covers (batch*320 + row).
// ---------------------------------------------------------------------------
template <typename VT>
__global__ void fuse_kernel(const VT* __restrict__ msrc,
                            const VT* __restrict__ gsrc,
                            VT* __restrict__ out,
                            int Dv, int GSv, int off2)
{
    int c = blockIdx.x * blockDim.x + threadIdx.x;
    if (c >= Dv) return;
    int t = blockIdx.y;
    int r = t % 320;
    int b = t / 320;

    VT v;
    if (r < NRW) {
        v = msrc[((long long)b * NRW + r) * Dv + c];
    } else {
        int k   = (r < NRW + KK) ? (r - NRW) : (r - NRW - KK);
        int off = (r < NRW + KK) ? 0 : off2;
        int e   = g_ent[b * KK + k];
        int col = c + off; if (col >= GSv) col -= GSv;
        v = gsrc[((long long)b * NRW + e) * GSv + col];
    }
    out[(long long)t * Dv + c] = v;
}

extern "C" void kernel_launch(void* const* d_in, const int* in_sizes, int n_in,
                              void* d_out, int out_size)
{
    const float* aux_rel = (const float*)d_in[0];   // (16,300,512)
    const float* cls_log = (const float*)d_in[1];   // (16,600,150)
    const float* pred_bb = (const float*)d_in[2];   // (16,600,4)
    const float* pro     = (const float*)d_in[3];   // (16,300,512)
    const float* roi     = (const float*)d_in[4];   // (16,300,12544)
    const float* so_cls  = (const float*)d_in[5];   // (16,300,300)
    const float* pb_so   = (const float*)d_in[6];   // (16,300,8)
    const float* so_pro  = (const float*)d_in[7];   // (16,300,512)
    const float* so_roi  = (const float*)d_in[8];   // (16,300,12544)
    const float* rel_lg  = (const float*)d_in[9];   // (16,300,50)
    const float* rel_ft  = (const float*)d_in[10];  // (16,300,256)
    const unsigned char* vis = (const unsigned char*)d_in[11]; // (16,300)

    float* out = (float*)d_out;

    select_kernel<<<NB, 512>>>(so_cls, rel_lg, pb_so, cls_log, pred_bb, vis,
                               out + O_VIS);

    const int ny = NB * 320;

    // so_pro_out: D=512 -> 128 float4, swap at 256 floats (64 f4)
    fuse_kernel<float4><<<dim3(1, ny), 128>>>(
        (const float4*)so_pro, (const float4*)pro,
        (float4*)(out + O_PRO), 128, 128, 64);

    // boxes_so_out: D=8 -> 2 float4, swap at 4 floats (1 f4)
    fuse_kernel<float4><<<dim3(1, ny), 32>>>(
        (const float4*)pb_so, (const float4*)pred_bb,
        (float4*)(out + O_BOX), 2, 2, 1);

    // so_cls_out: D=300 -> 150 float2, swap at 150 floats (75 f2)
    fuse_kernel<float2><<<dim3(1, ny), 160>>>(
        (const float2*)so_cls, (const float2*)cls_log,
        (float2*)(out + O_CLS), 150, 150, 75);

    // rel_out: D=256 -> 64 float4, gather src rows are 512 floats (128 f4),
    // second block reads at +256 floats (64 f4)
    fuse_kernel<float4><<<dim3(1, ny), 64>>>(
        (const float4*)rel_ft, (const float4*)aux_rel,
        (float4*)(out + O_REL), 64, 128, 64);

    // so_roi_out: D=12544 -> 3136 float4, swap at 6272 floats (1568 f4)
    fuse_kernel<float4><<<dim3((3136 + 255) / 256, ny), 256>>>(
        (const float4*)so_roi, (const float4*)roi,
        (float4*)(out + O_ROI), 3136, 3136, 1568);
}

// round 2
// speedup vs baseline: 2.7748x; 2.7748x over previous
#include <cuda_runtime.h>
#include <cuda_bf16.h>
#include <math.h>

// Problem constants
#define NB   16
#define NRW  300
#define CC   150
#define NREL 50
#define RR   3
#define RR2  9
#define NTRI 2700
#define MAXR 100
#define KK   10

// Output float offsets inside d_out
#define O_PRO   0LL
#define O_BOX   2621440LL
#define O_CLS   2662400LL
#define O_REL   4198400LL
#define O_ROI   5509120LL
#define O_VIS   69734400LL

#define FULLMASK 0xffffffffu

// Scratch
__device__ float g_tri[NB * NTRI];
__device__ int   g_scl[NB * NRW * 3];
__device__ int   g_ocl[NB * NRW * 3];
__device__ int   g_entcls[NB * NRW];
__device__ float g_entscore[NB * NRW];
__device__ float g_entbox[NB * NRW * 4];
__device__ int   g_ent[NB * KK];

__device__ __forceinline__ float sigmoidf_(float x) {
    return 1.0f / (1.0f + expf(-x));
}

__device__ __forceinline__ void warp_argmax_bcast(float& v, int& i) {
    #pragma unroll
    for (int o = 16; o; o >>= 1) {
        float ov = __shfl_down_sync(FULLMASK, v, o);
        int   oi = __shfl_down_sync(FULLMASK, i, o);
        if (ov > v || (ov == v && oi < i)) { v = ov; i = oi; }
    }
    v = __shfl_sync(FULLMASK, v, 0);
    i = __shfl_sync(FULLMASK, i, 0);
}

// Warp-cooperative top-3 over lane-strided values lv[k] at index c = lane+32k.
__device__ __forceinline__ void top3_warp(float lv[5], int lane,
                                          float outv[3], int outi[3]) {
    #pragma unroll
    for (int r = 0; r < 3; r++) {
        float bv = -1e30f; int bi = 0x7fffffff;
        #pragma unroll
        for (int k = 0; k < 5; k++) {
            int c = lane + 32 * k;
            if (lv[k] > bv) { bv = lv[k]; bi = c; }
        }
        warp_argmax_bcast(bv, bi);
        outv[r] = bv; outi[r] = bi;
        if ((bi & 31) == lane) lv[bi >> 5] = -1e30f;
    }
}

// ---------------------------------------------------------------------------
// Kernel P: warp per (b,i). Computes triple scores + entity info.
// ---------------------------------------------------------------------------
__global__ void __launch_bounds__(256) precompute_kernel(
    const float* __restrict__ so_cls,      // (NB,300,300)
    const float* __restrict__ rel_logits,  // (NB,300,50)
    const float* __restrict__ cls_logits,  // (NB,600,150)
    const float* __restrict__ pred_bb,     // (NB,600,4)
    const unsigned char* __restrict__ vis) // (NB,300)
{
    int gw   = (blockIdx.x * blockDim.x + threadIdx.x) >> 5;
    int lane = threadIdx.x & 31;
    if (gw >= NB * NRW) return;
    int b = gw / NRW, i = gw % NRW;

    const float* row = so_cls + (long long)gw * (2 * CC);

    float lv[5];
    // subject top-3
    #pragma unroll
    for (int k = 0; k < 5; k++) { int c = lane + 32 * k; lv[k] = (c < CC) ? row[c] : -1e30f; }
    float sv[3]; int si[3];
    top3_warp(lv, lane, sv, si);
    // object top-3
    #pragma unroll
    for (int k = 0; k < 5; k++) { int c = lane + 32 * k; lv[k] = (c < CC) ? row[CC + c] : -1e30f; }
    float ov[3]; int oi[3];
    top3_warp(lv, lane, ov, oi);

    // rel max
    const float* rl = rel_logits + (long long)gw * NREL;
    float m = -1e30f;
    #pragma unroll
    for (int k = 0; k < 2; k++) { int c = lane + 32 * k; if (c < NREL) m = fmaxf(m, rl[c]); }
    #pragma unroll
    for (int o = 16; o; o >>= 1) m = fmaxf(m, __shfl_down_sync(FULLMASK, m, o));
    m = __shfl_sync(FULLMASK, m, 0);
    float rmax = sigmoidf_(m);

    float ssig[3], osig[3];
    #pragma unroll
    for (int r = 0; r < 3; r++) { ssig[r] = sigmoidf_(sv[r]); osig[r] = sigmoidf_(ov[r]); }

    if (lane < 9) {
        int X = lane / 3, Y = lane % 3;
        float s = (X == 0) ? ssig[0] : (X == 1) ? ssig[1] : ssig[2];
        float o = (Y == 0) ? osig[0] : (Y == 1) ? osig[1] : osig[2];
        g_tri[gw * RR2 + lane] = (rmax * s) * o;
    }
    if (lane == 0) {
        #pragma unroll
        for (int r = 0; r < 3; r++) { g_scl[gw * 3 + r] = si[r]; g_ocl[gw * 3 + r] = oi[r]; }
    }

    // entity (row 2i of cls_logits / pred_bb)
    const float* crow = cls_logits + (long long)(b * 2 * NRW + 2 * i) * CC;
    float bv = -1e30f; int bi = 0x7fffffff;
    #pragma unroll
    for (int k = 0; k < 5; k++) {
        int c = lane + 32 * k;
        float v = (c < CC) ? crow[c] : -1e30f;
        if (v > bv) { bv = v; bi = c; }
    }
    warp_argmax_bcast(bv, bi);
    if (lane == 0) {
        g_entcls[gw] = bi;
        float sc = sigmoidf_(bv);
        if (vis[gw]) sc -= 2.0f;
        g_entscore[gw] = sc;
    }
    const float* bb = pred_bb + (long long)(b * 2 * NRW + 2 * i) * 4;
    if (lane < 4) g_entbox[gw * 4 + lane] = bb[lane];
}

// ---------------------------------------------------------------------------
// Kernel S: one block per batch. Radix top-100, IoU dedup, top-10 entities.
// ---------------------------------------------------------------------------
__global__ void __launch_bounds__(1024) select_kernel(
    const float* __restrict__ pb_so,       // (NB,300,8)
    const unsigned char* __restrict__ vis, // (NB,300)
    float* __restrict__ vis_out)
{
    const int b    = blockIdx.x;
    const int tid  = threadIdx.x;
    const int lane = tid & 31;
    const int wid  = tid >> 5;

    __shared__ unsigned      skey[NTRI];
    __shared__ unsigned char selflag[NTRI];
    __shared__ int           hist[256];
    __shared__ int           tri_idx_sh[MAXR];
    __shared__ int           selcls_sh[2 * MAXR];
    __shared__ float         selbox_sh[2 * MAXR][4];
    __shared__ float         entscore_sh[NRW];
    __shared__ unsigned char entflag_sh[NRW];
    __shared__ int           warpsum[32];
    __shared__ int           segbase_sh;
    __shared__ float         redv[32];
    __shared__ int           redi[32];

    // load keys
    for (int t = tid; t < NTRI; t += 1024)
        skey[t] = __float_as_uint(g_tri[b * NTRI + t]);
    if (tid == 0) segbase_sh = 0;
    __syncthreads();

    // ---- radix select: find 100th-largest key (exact) ----
    unsigned prefval = 0, prefmask = 0;
    int rem = MAXR;
    #pragma unroll
    for (int shift = 24; shift >= 0; shift -= 8) {
        if (tid < 256) hist[tid] = 0;
        __syncthreads();
        for (int t = tid; t < NTRI; t += 1024) {
            unsigned k = skey[t];
            if ((k & prefmask) == prefval)
                atomicAdd(&hist[(k >> shift) & 0xff], 1);
        }
        __syncthreads();
        int c = 0, d = 255;
        for (; d >= 0; --d) {
            int h = hist[d];
            if (c + h >= rem) break;
            c += h;
        }
        rem -= c;
        prefval  |= ((unsigned)d) << shift;
        prefmask |= 0xffu << shift;
        __syncthreads();
    }
    const unsigned thr = prefval;
    const int E = rem;  // number of equal-to-thr elements to take (smallest idx)

    // ---- flags: key > thr, or key == thr with eq-rank < E ----
    for (int seg = 0; seg < 3; seg++) {
        int t = seg * 1024 + tid;
        bool inb = t < NTRI;
        unsigned key = inb ? skey[t] : 0u;
        bool isEq = inb && (key == thr);
        unsigned bal = __ballot_sync(FULLMASK, isEq);
        if (lane == 0) warpsum[wid] = __popc(bal);
        __syncthreads();
        if (tid < 32) {
            int v = warpsum[tid];
            #pragma unroll
            for (int o = 1; o < 32; o <<= 1) {
                int n = __shfl_up_sync(FULLMASK, v, o);
                if (tid >= o) v += n;
            }
            warpsum[tid] = v;
        }
        __syncthreads();
        int wbase = wid ? warpsum[wid - 1] : 0;
        int eqrank = segbase_sh + wbase + __popc(bal & ((1u << lane) - 1));
        if (inb)
            selflag[t] = (key > thr) || (isEq && eqrank < E);
        __syncthreads();
        if (tid == 0) segbase_sh += warpsum[31];
        __syncthreads();
    }

    // ---- compaction (ascending index) by warp 0 ----
    if (tid < 32) {
        int total = 0;
        for (int s0 = 0; s0 < NTRI; s0 += 32) {
            int t = s0 + lane;
            bool f = (t < NTRI) && selflag[t];
            unsigned bal = __ballot_sync(FULLMASK, f);
            int pos = total + __popc(bal & ((1u << lane) - 1));
            if (f) tri_idx_sh[pos] = t;
            total += __popc(bal);
        }
    }
    __syncthreads();

    // ---- gather selected classes & boxes ----
    if (tid < MAXR) {
        int t = tri_idx_sh[tid];
        int i = t / RR2, p = t % RR2;
        int X = p / RR, Y = p % RR;
        selcls_sh[2 * tid]     = g_scl[(b * NRW + i) * 3 + X];
        selcls_sh[2 * tid + 1] = g_ocl[(b * NRW + i) * 3 + Y];
        const float* bx = pb_so + (long long)(b * NRW + i) * 8;
        selbox_sh[2 * tid][0]     = bx[0]; selbox_sh[2 * tid][1]     = bx[1];
        selbox_sh[2 * tid][2]     = bx[2]; selbox_sh[2 * tid][3]     = bx[3];
        selbox_sh[2 * tid + 1][0] = bx[4]; selbox_sh[2 * tid + 1][1] = bx[5];
        selbox_sh[2 * tid + 1][2] = bx[6]; selbox_sh[2 * tid + 1][3] = bx[7];
    }
    __syncthreads();

    // ---- IoU dedup: warp per entity ----
    for (int i = wid; i < NRW; i += 32) {
        int cls  = g_entcls[b * NRW + i];
        float x1 = g_entbox[(b * NRW + i) * 4 + 0];
        float y1 = g_entbox[(b * NRW + i) * 4 + 1];
        float x2 = g_entbox[(b * NRW + i) * 4 + 2];
        float y2 = g_entbox[(b * NRW + i) * 4 + 3];
        float a1 = (y2 - y1 + 1.0f) * (x2 - x1 + 1.0f);
        bool hit = false;
        for (int j = lane; j < 2 * MAXR; j += 32) {
            if (selcls_sh[j] != cls) continue;
            float bx1 = selbox_sh[j][0], by1 = selbox_sh[j][1];
            float bx2 = selbox_sh[j][2], by2 = selbox_sh[j][3];
            float a2  = (by2 - by1 + 1.0f) * (bx2 - bx1 + 1.0f);
            float ltx = fmaxf(x1, bx1), lty = fmaxf(y1, by1);
            float rbx = fminf(x2, bx2), rby = fminf(y2, by2);
            float w = fmaxf(rbx - ltx, 0.0f), h = fmaxf(rby - lty, 0.0f);
            float inter = w * h;
            float iou = inter / (a1 + a2 - inter);
            if (iou >= 0.5f) hit = true;
        }
        bool any = __any_sync(FULLMASK, hit);
        if (lane == 0) {
            float sc = g_entscore[b * NRW + i];
            if (any) sc -= 2.0f;
            entscore_sh[i] = sc;
            entflag_sh[i] = 0;
        }
    }
    __syncthreads();

    // ---- top-10 entities ----
    for (int it = 0; it < KK; it++) {
        float v = (tid < NRW && !entflag_sh[tid]) ? entscore_sh[tid] : -1e30f;
        int   i = (tid < NRW) ? tid : 0x7fffffff;
        #pragma unroll
        for (int o = 16; o; o >>= 1) {
            float ovv = __shfl_down_sync(FULLMASK, v, o);
            int   oii = __shfl_down_sync(FULLMASK, i, o);
            if (ovv > v || (ovv == v && oii < i)) { v = ovv; i = oii; }
        }
        if (lane == 0) { redv[wid] = v; redi[wid] = i; }
        __syncthreads();
        if (tid == 0) {
            float fv = redv[0]; int fi = redi[0];
            for (int w = 1; w < 32; w++)
                if (redv[w] > fv || (redv[w] == fv && redi[w] < fi)) { fv = redv[w]; fi = redi[w]; }
            entflag_sh[fi] = 1;
        }
        __syncthreads();
    }

    // ---- emit g_ent (ascending) + vis_out ----
    if (tid < 32) {
        int total = 0;
        for (int s0 = 0; s0 < NRW; s0 += 32) {
            int t = s0 + lane;
            bool f = (t < NRW) && entflag_sh[t];
            unsigned bal = __ballot_sync(FULLMASK, f);
            int pos = total + __popc(bal & ((1u << lane) - 1));
            if (f) g_ent[b * KK + pos] = t;
            total += __popc(bal);
        }
    }
    if (tid < NRW)
        vis_out[b * NRW + tid] = (vis[b * NRW + tid] || entflag_sh[tid]) ? 1.0f : 0.0f;
}

// ---------------------------------------------------------------------------
// Fuse kernels: flat 1D over output vector elements.
// rows [0,300): copy msrc; [300,310): gather g_ent col+0; [310,320): col+OFF2 mod GSV.
// ---------------------------------------------------------------------------
template <typename VT, int DV, int GSV, int OFF2>
__global__ void __launch_bounds__(256) fuse_kernel(
    const VT* __restrict__ msrc, const VT* __restrict__ gsrc, VT* __restrict__ out)
{
    long long idx = (long long)blockIdx.x * 256 + threadIdx.x;
    const long long total = (long long)NB * 320 * DV;
    if (idx >= total) return;
    int c = (int)(idx % DV);
    int t = (int)(idx / DV);
    int r = t % 320;
    int b = t / 320;

    VT v;
    if (r < NRW) {
        v = msrc[(long long)(b * NRW + r) * DV + c];
    } else {
        int k = r - NRW, off = 0;
        if (k >= KK) { k -= KK; off = OFF2; }
        int e = g_ent[b * KK + k];
        int col = c + off; if (col >= GSV) col -= GSV;
        v = gsrc[(long long)(b * NRW + e) * GSV + col];
    }
    out[idx] = v;
}

extern "C" void kernel_launch(void* const* d_in, const int* in_sizes, int n_in,
                              void* d_out, int out_size)
{
    const float* aux_rel = (const float*)d_in[0];
    const float* cls_log = (const float*)d_in[1];
    const float* pred_bb = (const float*)d_in[2];
    const float* pro     = (const float*)d_in[3];
    const float* roi     = (const float*)d_in[4];
    const float* so_cls  = (const float*)d_in[5];
    const float* pb_so   = (const float*)d_in[6];
    const float* so_pro  = (const float*)d_in[7];
    const float* so_roi  = (const float*)d_in[8];
    const float* rel_lg  = (const float*)d_in[9];
    const float* rel_ft  = (const float*)d_in[10];
    const unsigned char* vis = (const unsigned char*)d_in[11];

    float* out = (float*)d_out;

    precompute_kernel<<<(NB * NRW * 32 + 255) / 256, 256>>>(
        so_cls, rel_lg, cls_log, pred_bb, vis);

    select_kernel<<<NB, 1024>>>(pb_so, vis, out + O_VIS);

    // so_pro_out: 128 f4/row, swap 64
    fuse_kernel<float4, 128, 128, 64><<<(NB * 320 * 128 + 255) / 256, 256>>>(
        (const float4*)so_pro, (const float4*)pro, (float4*)(out + O_PRO));
    // boxes: 2 f4/row, swap 1
    fuse_kernel<float4, 2, 2, 1><<<(NB * 320 * 2 + 255) / 256, 256>>>(
        (const float4*)pb_so, (const float4*)pred_bb, (float4*)(out + O_BOX));
    // cls: 150 f2/row, swap 75
    fuse_kernel<float2, 150, 150, 75><<<(NB * 320 * 150 + 255) / 256, 256>>>(
        (const float2*)so_cls, (const float2*)cls_log, (float2*)(out + O_CLS));
    // rel: 64 f4/row out, gather rows 128 f4 wide, second block at +64
    fuse_kernel<float4, 64, 128, 64><<<(NB * 320 * 64 + 255) / 256, 256>>>(
        (const float4*)rel_ft, (const float4*)aux_rel, (float4*)(out + O_REL));
    // roi: 3136 f4/row, swap 1568
    fuse_kernel<float4, 3136, 3136, 1568><<<(NB * 320 * 3136 + 255) / 256, 256>>>(
        (const float4*)so_roi, (const float4*)roi, (float4*)(out + O_ROI));
}